// round 2
// baseline (speedup 1.0000x reference)
#include <cuda_runtime.h>
#include <math.h>

#define BB 8
#define NHEADS 16
#define DH 48
#define DD 768
#define P2 256

// Scratch: windowified Q/K/V  [b][head][n][pix4][dh]  (25MB each)
__device__ float g_Q[BB*NHEADS*P2*4*DH];
__device__ float g_K[BB*NHEADS*P2*4*DH];
__device__ float g_V[BB*NHEADS*P2*4*DH];
// BN-folded conv weights: g_ws[(j*25+tap)*768 + c], bias g_wb[j*768+c]
__device__ float g_ws[3*25*DD];
__device__ float g_wb[3*DD];

// ---------------------------------------------------------------------------
// Fold BN into depthwise conv weights.
// conv_w layout: (3, 768, 1, 5, 5) -> flat (j*768+c)*25 + tap
// ---------------------------------------------------------------------------
__global__ void prep_kernel(const float* __restrict__ conv_w,
                            const float* __restrict__ gamma,
                            const float* __restrict__ beta,
                            const float* __restrict__ mean,
                            const float* __restrict__ var) {
    int t = blockIdx.x * blockDim.x + threadIdx.x;
    if (t >= 3 * DD) return;
    int j = t / DD;
    int c = t % DD;
    float inv = gamma[t] * rsqrtf(var[t] + 1e-5f);
    g_wb[t] = beta[t] - mean[t] * inv;
    const float* w = conv_w + (size_t)t * 25;
#pragma unroll
    for (int tap = 0; tap < 25; tap++)
        g_ws[(j * 25 + tap) * DD + c] = w[tap] * inv;
}

// ---------------------------------------------------------------------------
// Fused depthwise 5x5 conv + BN for q,k,v.
// x: (b, 1024, 768) channels-last. Output written windowified:
//   image pixel (r,cl): n = (r%16)*16 + (cl%16), pix = (r/16)*2 + (cl/16)
// Block: 256 thr = 32 channels x 8 slots. Grid: (24 chunks * 4 rowquads, 8 b).
// Each thread: 4 groups of (1 row x 8 cols), 3 convs fused, weights in regs.
// ---------------------------------------------------------------------------
__global__ __launch_bounds__(256) void conv_kernel(const float* __restrict__ x) {
    int b     = blockIdx.y;
    int chunk = blockIdx.x >> 2;
    int rquad = blockIdx.x & 3;
    int lane5 = threadIdx.x & 31;
    int slot  = threadIdx.x >> 5;
    int c     = chunk * 32 + lane5;
    int head  = c / DH;
    int cc    = c % DH;

    float w[3][25], bias[3];
#pragma unroll
    for (int j = 0; j < 3; j++) {
        bias[j] = g_wb[j * DD + c];
#pragma unroll
        for (int tp = 0; tp < 25; tp++) w[j][tp] = g_ws[(j * 25 + tp) * DD + c];
    }

    const float* xb = x + (size_t)b * 1024 * DD + c;

#pragma unroll 1
    for (int gi = 0; gi < 4; gi++) {
        int g    = slot * 4 + gi;       // 0..31
        int row  = rquad * 8 + (g >> 2);
        int col0 = (g & 3) * 8;

        float acc[3][8];
#pragma unroll
        for (int j = 0; j < 3; j++)
#pragma unroll
            for (int o = 0; o < 8; o++) acc[j][o] = 0.f;

#pragma unroll
        for (int dy = 0; dy < 5; dy++) {
            int r = row + dy - 2;
            if ((unsigned)r < 32u) {
                const float* xr = xb + (size_t)(r * 32) * DD;
                float xv[12];
#pragma unroll
                for (int i = 0; i < 12; i++) {
                    int cl = col0 + i - 2;
                    xv[i] = ((unsigned)cl < 32u) ? xr[cl * DD] : 0.f;
                }
#pragma unroll
                for (int j = 0; j < 3; j++) {
#pragma unroll
                    for (int dx = 0; dx < 5; dx++) {
                        float wv = w[j][dy * 5 + dx];
#pragma unroll
                        for (int o = 0; o < 8; o++) acc[j][o] += wv * xv[o + dx];
                    }
                }
            }
        }

        // col group never crosses the 16-boundary (col0 in {0,8,16,24})
        int pix   = ((row >> 4) << 1) + (col0 >> 4);
        int nbase = (row & 15) * 16 + (col0 & 15);
        int obase = (((b * NHEADS + head) * P2 + nbase) * 4 + pix) * DH + cc;
#pragma unroll
        for (int o = 0; o < 8; o++) {
            int off = obase + o * (4 * DH);   // n increments by 1 per o
            g_Q[off] = acc[0][o] + bias[0];
            g_K[off] = acc[1][o] + bias[1];
            g_V[off] = acc[2][o] + bias[2];
        }
    }
}

// ---------------------------------------------------------------------------
// Fused top-8 + sparse window attention. One warp per (b, head, window n).
// Block = 4 warps (independent windows). No cross-warp sharing.
// ---------------------------------------------------------------------------
struct WarpSmem {
    float vbuf[32 * 52 + 64];  // v staged, stride 52 (pad: conflict-free + f4-aligned)
    float qs[4 * 48];          // q * scale
    float at[128];             // softmax weights, [kk][qp] (float4 per kk)
};

__global__ __launch_bounds__(128) void attn_kernel(const float* __restrict__ adj,
                                                   float* __restrict__ out) {
    __shared__ __align__(16) WarpSmem sm[4];
    const unsigned FULL = 0xffffffffu;
    int warp = threadIdx.x >> 5;
    int lane = threadIdx.x & 31;
    int widx = blockIdx.x * 4 + warp;      // 0..32767
    int bh   = widx >> 8;
    int n    = widx & 255;
    int b    = bh >> 4;
    int head = bh & 15;
    WarpSmem& S = sm[warp];

    // ---- top-8 of gen_adj row (256 values, 8 per lane) ----
    const float* rowp = adj + ((size_t)bh * 256 + n) * 256;
    float vals[8];
#pragma unroll
    for (int j = 0; j < 8; j++) vals[j] = rowp[j * 32 + lane];

    int mysel = 0;
    for (int it = 0; it < 8; it++) {
        float bv = -1e30f;
        int bi = 0;
#pragma unroll
        for (int j = 0; j < 8; j++)
            if (vals[j] > bv) { bv = vals[j]; bi = j * 32 + lane; }
#pragma unroll
        for (int off = 16; off > 0; off >>= 1) {
            float ov = __shfl_down_sync(FULL, bv, off);
            int   oi = __shfl_down_sync(FULL, bi, off);
            if (ov > bv) { bv = ov; bi = oi; }
        }
        bi = __shfl_sync(FULL, bi, 0);
        if (lane == it) mysel = bi;
#pragma unroll
        for (int j = 0; j < 8; j++)
            if (bi == j * 32 + lane) vals[j] = -1e30f;
    }

    // ---- stage q (scaled) into smem ----
    const float scale = 0.03608439182435161f;  // 768^-0.5
    {
        const float4* qsrc = (const float4*)(g_Q + (size_t)widx * 192);
        float4 t = qsrc[lane];
        t.x *= scale; t.y *= scale; t.z *= scale; t.w *= scale;
        ((float4*)S.qs)[lane] = t;
        if (lane < 16) {
            float4 t2 = qsrc[32 + lane];
            t2.x *= scale; t2.y *= scale; t2.z *= scale; t2.w *= scale;
            ((float4*)S.qs)[32 + lane] = t2;
        }
    }

    // ---- gather: lane kk = sel*4 + pix. k -> regs, v -> smem ----
    int sel  = __shfl_sync(FULL, mysel, lane >> 2);
    int base = ((bh * 256 + sel) * 4 + (lane & 3)) * DH;
    float kreg[48];
    {
        const float4* kp = (const float4*)(g_K + base);
#pragma unroll
        for (int i = 0; i < 12; i++) {
            float4 t = kp[i];
            kreg[4*i] = t.x; kreg[4*i+1] = t.y; kreg[4*i+2] = t.z; kreg[4*i+3] = t.w;
        }
        const float4* vp = (const float4*)(g_V + base);
        float4* vd = (float4*)(&S.vbuf[lane * 52]);
#pragma unroll
        for (int i = 0; i < 12; i++) vd[i] = vp[i];
    }
    __syncwarp();

    // ---- logits[qp] for this lane's key column (dot over 48) ----
    float l[4] = {0.f, 0.f, 0.f, 0.f};
#pragma unroll
    for (int ch = 0; ch < 12; ch++) {
#pragma unroll
        for (int qp = 0; qp < 4; qp++) {
            float4 qv = ((const float4*)&S.qs[qp * 48])[ch];
            l[qp] += qv.x * kreg[4*ch] + qv.y * kreg[4*ch+1]
                   + qv.z * kreg[4*ch+2] + qv.w * kreg[4*ch+3];
        }
    }

    // ---- softmax across 32 lanes per qp-row ----
    float a[4];
#pragma unroll
    for (int qp = 0; qp < 4; qp++) {
        float m = l[qp];
#pragma unroll
        for (int off = 16; off > 0; off >>= 1)
            m = fmaxf(m, __shfl_xor_sync(FULL, m, off));
        float e = __expf(l[qp] - m);
        float s = e;
#pragma unroll
        for (int off = 16; off > 0; off >>= 1)
            s += __shfl_xor_sync(FULL, s, off);
        a[qp] = __fdividef(e, s);
    }
    ((float4*)S.at)[lane] = make_float4(a[0], a[1], a[2], a[3]);
    __syncwarp();

    // ---- out[qp][c] = sum_kk a[qp][kk] * v[kk][c]; lane owns c=lane (+c=32+lane for lane<16)
    float o1[4] = {0,0,0,0}, o2[4] = {0,0,0,0};
#pragma unroll
    for (int kk = 0; kk < 32; kk++) {
        float4 av = ((const float4*)S.at)[kk];          // broadcast
        float v1 = S.vbuf[kk * 52 + lane];
        float v2 = S.vbuf[kk * 52 + 32 + lane];         // garbage for lane>=16, never stored
        o1[0] += av.x * v1; o1[1] += av.y * v1; o1[2] += av.z * v1; o1[3] += av.w * v1;
        o2[0] += av.x * v2; o2[1] += av.y * v2; o2[2] += av.z * v2; o2[3] += av.w * v2;
    }

    // ---- scatter to output: row = (p&1)*16 + wy, col = (p>>1)*16 + wx ----
    int wy = n >> 4, wx = n & 15;
    float* ob = out + (size_t)b * 1024 * 768 + head * 48;
#pragma unroll
    for (int p = 0; p < 4; p++) {
        int row = ((p & 1) << 4) + wy;
        int col = ((p >> 1) << 4) + wx;
        int off = (row * 32 + col) * 768;
        ob[off + lane] = o1[p];
        if (lane < 16) ob[off + 32 + lane] = o2[p];
    }
}

// ---------------------------------------------------------------------------
extern "C" void kernel_launch(void* const* d_in, const int* in_sizes, int n_in,
                              void* d_out, int out_size) {
    const float* x      = (const float*)d_in[0];
    // d_in[1] = noise (unused by reference)
    const float* adj    = (const float*)d_in[2];
    const float* conv_w = (const float*)d_in[3];
    const float* gamma  = (const float*)d_in[4];
    const float* beta   = (const float*)d_in[5];
    const float* mean   = (const float*)d_in[6];
    const float* var    = (const float*)d_in[7];
    // d_in[8] = sparsity (constant 8, compiled in)
    float* out = (float*)d_out;

    prep_kernel<<<9, 256>>>(conv_w, gamma, beta, mean, var);
    conv_kernel<<<dim3(96, 8), 256>>>(x);
    attn_kernel<<<8192, 128>>>(adj, out);
}